// round 15
// baseline (speedup 1.0000x reference)
#include <cuda_runtime.h>
#include <mma.h>
#include <cuda_fp16.h>
#include <cstdint>

using namespace nvcuda;

#define NB 64
#define NP 16
#define NT 256
#define NI 256
#define NH 512
#define NO 5
#define NK (NP*NI)   /* 4096 */
#define NV 50000

// Scratch (device globals per harness rules)
__device__ float  g_pre[4][NT][NB][NH];   // [gate][t][b][h]
__device__ __half g_embH[NV * NI];        // fp16 embedding table
__device__ __half g_WcH[4][NK][NH];       // fp16 x-weights (natural layout)
__device__ __half g_hh[2][NB*NH];         // fp16 hidden state ping-pong
__device__ float  g_h_final[NB*NH];
__device__ int    g_count;

__device__ __forceinline__ uint32_t smem_u32(const void* p) {
    uint32_t a;
    asm("{ .reg .u64 t; cvta.to.shared.u64 t, %1; cvt.u32.u64 %0, t; }" : "=r"(a) : "l"(p));
    return a;
}
#define CP_ASYNC_16(dst, src) \
    asm volatile("cp.async.cg.shared.global [%0], [%1], 16;" :: "r"(dst), "l"(src))
#define CP_ASYNC_16_PRED(dst, src, nbytes) \
    asm volatile("cp.async.cg.shared.global [%0], [%1], 16, %2;" :: "r"(dst), "l"(src), "r"(nbytes))
#define CP_COMMIT() asm volatile("cp.async.commit_group;" ::: "memory")
#define CP_WAIT(n)  asm volatile("cp.async.wait_group %0;" :: "n"(n) : "memory")
#define CP_WAIT_ALL() asm volatile("cp.async.wait_all;" ::: "memory")

#define LDMATRIX_X4(a0, a1, a2, a3, addr) \
    asm volatile("ldmatrix.sync.aligned.m8n8.x4.shared.b16 {%0,%1,%2,%3}, [%4];" \
                 : "=r"(a0), "=r"(a1), "=r"(a2), "=r"(a3) : "r"(addr))

#define MMA_16816(d, a0, a1, a2, a3, b0, b1) \
    asm volatile("mma.sync.aligned.m16n8k16.row.col.f32.f16.f16.f32 " \
                 "{%0,%1,%2,%3}, {%4,%5,%6,%7}, {%8,%9}, {%0,%1,%2,%3};" \
                 : "+f"((d)[0]), "+f"((d)[1]), "+f"((d)[2]), "+f"((d)[3]) \
                 : "r"(a0), "r"(a1), "r"(a2), "r"(a3), "r"(b0), "r"(b1))

__device__ __forceinline__ float fast_sigmoid(float x) {
    return 1.f / (1.f + __expf(-x));
}
__device__ __forceinline__ float fast_tanh(float x) {
    return 2.f / (1.f + __expf(-2.f * x)) - 1.f;
}

// ===================== prep: fp32 -> fp16 =====================
__global__ __launch_bounds__(256) void convert_emb(const float* __restrict__ emb) {
    long idx = (long)blockIdx.x * blockDim.x + threadIdx.x;
    long n = (long)NV * NI;
    for (; idx < n; idx += (long)gridDim.x * blockDim.x)
        g_embH[idx] = __float2half_rn(emb[idx]);
}
__global__ __launch_bounds__(256) void convert_wx(const float* __restrict__ w0,
                                                  const float* __restrict__ w1,
                                                  const float* __restrict__ w2,
                                                  const float* __restrict__ w3) {
    const float* W = (blockIdx.y == 0) ? w0 : (blockIdx.y == 1) ? w1 : (blockIdx.y == 2) ? w2 : w3;
    long idx = (long)blockIdx.x * blockDim.x + threadIdx.x;
    long n = (long)NK * NH;
    for (; idx < n; idx += (long)gridDim.x * blockDim.x)
        g_WcH[blockIdx.y][0][idx] = __float2half_rn(W[idx]);
}

__global__ __launch_bounds__(256) void init_state() {
    int idx = blockIdx.x * blockDim.x + threadIdx.x;
    if (idx < NB * NH) { g_hh[0][idx] = __ushort_as_half((unsigned short)0); }
    if (idx == 0) g_count = 0;
}

// ===================== pre-activation GEMM (fp16 WMMA, 512 thr) =============
// CTA: M=128 (2 t x 64 b) x N=256, K=4096 in 64 slabs of 64. 3-stage cp.async,
// single __syncthreads per slab. 16 warps (4/SMSP), warp tile 32x64.
#define A_LDH 72                              /* halves */
#define B_LDH 264
#define A_BYTES (128 * A_LDH * 2)             /* 18432 */
#define B_BYTES (64 * B_LDH * 2)              /* 33792 */
#define STAGE_BYTES (A_BYTES + B_BYTES)       /* 52224 */
#define TOK_BYTES 8192
#define PRE_SMEM (TOK_BYTES + 3 * STAGE_BYTES)    /* 164864 */

__global__ __launch_bounds__(512) void pre_kernel(const int* __restrict__ x) {
    extern __shared__ char smem[];
    int* sTok = (int*)smem;
    const uint32_t stage0 = smem_u32(smem + TOK_BYTES);

    const int tid  = threadIdx.x;
    const int gate = blockIdx.x >> 1;
    const int h0   = (blockIdx.x & 1) * 256;
    const int t0   = blockIdx.y * 2;

    #pragma unroll
    for (int e = 0; e < 4; e++) {
        int idx = e * 512 + tid;
        int tt = idx >> 10, rem = idx & 1023;
        int p = rem >> 6, b = rem & 63;
        sTok[idx] = x[b * (NP * NT) + p * NT + (t0 + tt)];
    }
    __syncthreads();

    const __half* Wbase = &g_WcH[gate][0][h0];

    auto issue_slab = [&](int s, int st) {
        const uint32_t aB = stage0 + st * STAGE_BYTES;
        const uint32_t bB = aB + A_BYTES;
        const int p  = s >> 2;
        const int i0 = (s & 3) * 64;
        // A: 128 rows x 64 halves = 1024 chunks -> 2/thread
        #pragma unroll
        for (int e = 0; e < 2; e++) {
            int idx = e * 512 + tid;
            int row = idx >> 3, c8 = idx & 7;
            int tok = sTok[(row >> 6) * 1024 + p * 64 + (row & 63)];
            const __half* src = g_embH + (long)tok * NI + i0 + c8 * 8;
            CP_ASYNC_16_PRED(aB + (row * A_LDH + c8 * 8) * 2, src, tok ? 16 : 0);
        }
        // B: 64 rows x 256 halves = 2048 chunks -> 4/thread
        const int k0 = s * 64;
        #pragma unroll
        for (int e = 0; e < 4; e++) {
            int idx = e * 512 + tid;
            int row = idx >> 5, c8 = idx & 31;
            const __half* src = Wbase + (long)(k0 + row) * NH + c8 * 8;
            CP_ASYNC_16(bB + (row * B_LDH + c8 * 8) * 2, src);
        }
        CP_COMMIT();
    };

    const int w  = tid >> 5;
    const int m0 = (w & 3) * 32;                 // 4 m-tiles of 32
    const int n0 = (w >> 2) * 64;                // 4 n-tiles of 64

    wmma::fragment<wmma::accumulator, 16, 16, 16, float> acc[2][4];
    #pragma unroll
    for (int i = 0; i < 2; i++)
        #pragma unroll
        for (int j = 0; j < 4; j++) wmma::fill_fragment(acc[i][j], 0.f);

    issue_slab(0, 0);
    issue_slab(1, 1);

    for (int s = 0; s < 64; s++) {
        CP_WAIT(1);
        __syncthreads();
        if (s + 2 < 64) issue_slab(s + 2, (s + 2) % 3);
        else CP_COMMIT();

        const char* base = smem + TOK_BYTES + (s % 3) * STAGE_BYTES;
        const __half* bA = (const __half*)base;
        const __half* bB = (const __half*)(base + A_BYTES);

        #pragma unroll
        for (int kk = 0; kk < 4; kk++) {
            wmma::fragment<wmma::matrix_a, 16, 16, 16, __half, wmma::row_major> fa[2];
            wmma::fragment<wmma::matrix_b, 16, 16, 16, __half, wmma::row_major> fb[4];
            #pragma unroll
            for (int i = 0; i < 2; i++)
                wmma::load_matrix_sync(fa[i], bA + (m0 + i * 16) * A_LDH + kk * 16, A_LDH);
            #pragma unroll
            for (int j = 0; j < 4; j++)
                wmma::load_matrix_sync(fb[j], bB + (kk * 16) * B_LDH + n0 + j * 16, B_LDH);
            #pragma unroll
            for (int i = 0; i < 2; i++)
                #pragma unroll
                for (int j = 0; j < 4; j++)
                    wmma::mma_sync(acc[i][j], fa[i], fb[j], acc[i][j]);
        }
    }

    #pragma unroll
    for (int i = 0; i < 2; i++) {
        int m = m0 + i * 16;
        int t = t0 + (m >> 6);
        int b0 = m & 63;
        #pragma unroll
        for (int j = 0; j < 4; j++)
            wmma::store_matrix_sync(&g_pre[gate][t][b0][h0 + n0 + j * 16],
                                    acc[i][j], NH, wmma::mem_row_major);
    }
}

// ===================== persistent recurrence (warp-private staging) ==========
// 128 CTAs x 256 threads. CTA owns 4 h-cols x 4 gates (N=16). 8 warps =
// 4 m-tiles x 2 K-halves. Each warp stages ONLY its own 16-row x 256-col h
// slice and proceeds without CTA-wide sync. B in registers across all steps.
#define R_SW_LD 24                              /* halves */
#define R_SH_LD 520
#define R_SW_BYTES (512 * R_SW_LD * 2)          /* 24576 */
#define R_SH_BYTES (64 * R_SH_LD * 2)           /* 66560 */
#define R_SACC_OFF (R_SW_BYTES + R_SH_BYTES)    /* 91136 */
#define R_ACC_LD 20
#define R_WL_OFF (R_SACC_OFF + 2 * 64 * R_ACC_LD * 4)   /* 101376 */
#define REC_SMEM (R_WL_OFF + 512 * NO * 4)              /* 111616 */
#define RCTAS 128

__global__ __launch_bounds__(256) void rec_kernel(const float* __restrict__ Wfh,
                                                  const float* __restrict__ Wih,
                                                  const float* __restrict__ Wgh,
                                                  const float* __restrict__ Woh,
                                                  const float* __restrict__ bfp,
                                                  const float* __restrict__ bip,
                                                  const float* __restrict__ bgp,
                                                  const float* __restrict__ bop,
                                                  const float* __restrict__ Wl,
                                                  const float* __restrict__ bl,
                                                  float* __restrict__ out,
                                                  int out_size) {
    extern __shared__ char smraw[];
    __half* sW   = (__half*)smraw;                   // [512][24], col = gate*4+c
    __half* sH   = (__half*)(smraw + R_SW_BYTES);    // [64][520]
    float*  sAcc = (float*)(smraw + R_SACC_OFF);     // [2][64][20]

    const int cta = blockIdx.x;
    const int tid = threadIdx.x;
    const int lane = tid & 31;
    const int colbase = cta * 4;
    int* const pcnt = &g_count;

    {
        const float* Wp[4] = {Wfh, Wih, Wgh, Woh};
        #pragma unroll 8
        for (int e = 0; e < 32; e++) {
            int idx = e * 256 + tid;
            int row = idx >> 4, c = idx & 15;
            float v = Wp[c >> 2][row * NH + colbase + (c & 3)];
            sW[row * R_SW_LD + c] = __float2half_rn(v);
        }
    }
    __syncthreads();

    const int w     = tid >> 5;
    const int mwarp = (w & 3) * 16;
    const int kh    = w >> 2;
    const int kbase = kh * 256;

    uint32_t Breg[16][2][2];
    {
        const int kq = (lane & 3) * 2;
        const int nb = lane >> 2;
        #pragma unroll
        for (int s = 0; s < 16; s++) {
            int k0 = kbase + s * 16 + kq;
            #pragma unroll
            for (int nf = 0; nf < 2; nf++) {
                int n = nf * 8 + nb;
                __half2 v0 = __halves2half2(sW[(k0 + 0) * R_SW_LD + n],
                                            sW[(k0 + 1) * R_SW_LD + n]);
                __half2 v1 = __halves2half2(sW[(k0 + 8) * R_SW_LD + n],
                                            sW[(k0 + 9) * R_SW_LD + n]);
                Breg[s][nf][0] = *reinterpret_cast<uint32_t*>(&v0);
                Breg[s][nf][1] = *reinterpret_cast<uint32_t*>(&v1);
            }
        }
    }

    const int b  = tid >> 2;
    const int c  = tid & 3;
    const float bfv = bfp[colbase + c];
    const float biv = bip[colbase + c];
    const float bgv = bgp[colbase + c];
    const float bov = bop[colbase + c];
    float c_reg = 0.f;

    const uint32_t sHa = smem_u32(sH);
    const uint32_t stageDst = sHa + (kbase + lane * 8) * 2;
    const uint32_t ldmAddrBase = sHa + ((mwarp + (lane & 15)) * R_SH_LD + kbase + (lane >> 4) * 8) * 2;

    for (int t = 0; t < NT; t++) {
        const float pf  = g_pre[0][t][b][colbase + c];
        const float pi  = g_pre[1][t][b][colbase + c];
        const float pg_ = g_pre[2][t][b][colbase + c];
        const float po  = g_pre[3][t][b][colbase + c];

        if (t > 0) {
            if (tid == 0) {
                int target = RCTAS * t, v;
                do {
                    asm volatile("ld.acquire.gpu.b32 %0, [%1];" : "=r"(v) : "l"(pcnt) : "memory");
                } while (v < target);
            }
            __syncthreads();
        }

        const __half* hin = g_hh[t & 1] + kbase + lane * 8;
        #pragma unroll
        for (int ch = 0; ch < 16; ch++) {
            CP_ASYNC_16(stageDst + (mwarp + ch) * (R_SH_LD * 2),
                        hin + (mwarp + ch) * NH);
        }
        CP_COMMIT();
        CP_WAIT_ALL();
        __syncwarp();

        float acc[2][2][4];
        #pragma unroll
        for (int nf = 0; nf < 2; nf++)
            #pragma unroll
            for (int pq = 0; pq < 2; pq++)
                #pragma unroll
                for (int j = 0; j < 4; j++) acc[nf][pq][j] = 0.f;

        #pragma unroll
        for (int s = 0; s < 16; s++) {
            uint32_t a0, a1, a2, a3;
            LDMATRIX_X4(a0, a1, a2, a3, ldmAddrBase + s * 32);
            MMA_16816(acc[0][s & 1], a0, a1, a2, a3, Breg[s][0][0], Breg[s][0][1]);
            MMA_16816(acc[1][s & 1], a0, a1, a2, a3, Breg[s][1][0], Breg[s][1][1]);
        }

        {
            int r0 = lane >> 2, cc0 = (lane & 3) * 2;
            #pragma unroll
            for (int nf = 0; nf < 2; nf++) {
                float2 v0 = make_float2(acc[nf][0][0] + acc[nf][1][0],
                                        acc[nf][0][1] + acc[nf][1][1]);
                float2 v1 = make_float2(acc[nf][0][2] + acc[nf][1][2],
                                        acc[nf][0][3] + acc[nf][1][3]);
                int n = nf * 8 + cc0;
                *reinterpret_cast<float2*>(sAcc + (kh * 64 + mwarp + r0) * R_ACC_LD + n) = v0;
                *reinterpret_cast<float2*>(sAcc + (kh * 64 + mwarp + r0 + 8) * R_ACC_LD + n) = v1;
            }
        }
        __syncthreads();

        const float* a0p = sAcc + b * R_ACC_LD;
        const float* a1p = sAcc + (64 + b) * R_ACC_LD;
        float af = a0p[0 * 4 + c] + a1p[0 * 4 + c];
        float ai = a0p[1 * 4 + c] + a1p[1 * 4 + c];
        float ag = a0p[2 * 4 + c] + a1p[2 * 4 + c];
        float ao = a0p[3 * 4 + c] + a1p[3 * 4 + c];

        float f = fast_sigmoid(pf + bfv + af);
        float i = fast_sigmoid(pi + biv + ai);
        float g = fast_tanh(pg_ + bgv + ag);
        float o = fast_sigmoid(po + bov + ao);

        c_reg = f * c_reg + i * g;
        float hv = o * fast_tanh(c_reg);

        __half* hout = g_hh[(t + 1) & 1];
        __stcg(hout + b * NH + colbase + c, __float2half_rn(hv));
        if (t == NT - 1) {
            g_h_final[b * NH + colbase + c] = hv;
            int hidx = NB * NO + b * NH + colbase + c;
            int cidx = NB * NO + NB * NH + b * NH + colbase + c;
            if (hidx < out_size) out[hidx] = hv;
            if (cidx < out_size) out[cidx] = c_reg;
        }

        __syncthreads();
        if (tid == 0) {
            asm volatile("red.release.gpu.add.s32 [%0], %1;" :: "l"(pcnt), "r"(1) : "memory");
        }
    }

    // ---- head: CTA 0 computes out = h_final @ W_lin + b_lin ----
    if (cta == 0) {
        float* sWl = (float*)(smraw + R_WL_OFF);
        for (int idx = tid; idx < NH * NO; idx += 256)
            sWl[idx] = Wl[idx];
        if (tid == 0) {
            int target = RCTAS * NT, v;
            do {
                asm volatile("ld.acquire.gpu.b32 %0, [%1];" : "=r"(v) : "l"(pcnt) : "memory");
            } while (v < target);
        }
        __syncthreads();
        for (int idx = tid; idx < NB * NO; idx += 256) {
            int bb = idx / NO, o = idx % NO;
            float s = bl[o];
            #pragma unroll 8
            for (int k = 0; k < NH; k++) s += g_h_final[bb * NH + k] * sWl[k * NO + o];
            if (idx < out_size) out[idx] = s;
        }
    }
}

// ===================== launch =====================
extern "C" void kernel_launch(void* const* d_in, const int* in_sizes, int n_in,
                              void* d_out, int out_size) {
    const int*   x   = (const int*)  d_in[0];
    const float* emb = (const float*)d_in[1];
    const float* Wfx = (const float*)d_in[2];
    const float* Wfh = (const float*)d_in[3];
    const float* bf  = (const float*)d_in[4];
    const float* Wix = (const float*)d_in[5];
    const float* Wih = (const float*)d_in[6];
    const float* bi  = (const float*)d_in[7];
    const float* Wgx = (const float*)d_in[8];
    const float* Wgh = (const float*)d_in[9];
    const float* bg  = (const float*)d_in[10];
    const float* Wox = (const float*)d_in[11];
    const float* Woh = (const float*)d_in[12];
    const float* bo  = (const float*)d_in[13];
    const float* Wl  = (const float*)d_in[14];
    const float* bl  = (const float*)d_in[15];
    float* out = (float*)d_out;

    cudaFuncSetAttribute(pre_kernel, cudaFuncAttributeMaxDynamicSharedMemorySize, PRE_SMEM);
    cudaFuncSetAttribute(rec_kernel, cudaFuncAttributeMaxDynamicSharedMemorySize, REC_SMEM);

    convert_emb<<<2048, 256>>>(emb);
    convert_wx<<<dim3(1024, 4), 256>>>(Wfx, Wix, Wgx, Wox);
    init_state<<<(NB * NH + 255) / 256, 256>>>();

    pre_kernel<<<dim3(8, 128), 512, PRE_SMEM>>>(x);

    rec_kernel<<<RCTAS, 256, REC_SMEM>>>(Wfh, Wih, Wgh, Woh, bf, bi, bg, bo,
                                         Wl, bl, out, out_size);
}